// round 6
// baseline (speedup 1.0000x reference)
#include <cuda_runtime.h>
#include <cuda_bf16.h>

#define IN_FEATURES  256
#define OUT_FEATURES 4096
#define BATCH        8192

#define J_PER_CTA    1024   // 256 threads x 4 j
#define R_PER_CTA    4      // batch rows per CTA

// Packed per-out-feature params: {mean, inv_var, coef, src_index_as_bits}
__device__ float4 g_table[OUT_FEATURES];

// Prologue: one thread per float4 of expansion_mapping (4096x256/4 = 256K threads).
__global__ void build_table_kernel(const float4* __restrict__ em4,
                                   const float* __restrict__ means,
                                   const float* __restrict__ vars_,
                                   const float* __restrict__ coefs) {
    int tid = blockIdx.x * blockDim.x + threadIdx.x;    // [0, OUT*IN/4)
    float4 e = em4[tid];
    int base_i = (tid & (IN_FEATURES / 4 - 1)) * 4;
    int j = tid >> 6;                                    // IN_FEATURES/4 = 64
    int hit = -1;
    if (e.x > 0.5f) hit = base_i + 0;
    if (e.y > 0.5f) hit = base_i + 1;
    if (e.z > 0.5f) hit = base_i + 2;
    if (e.w > 0.5f) hit = base_i + 3;
    if (hit >= 0) {
        float4 t;
        t.x = __ldg(&means[j]);
        t.y = 1.0f / __ldg(&vars_[j]);
        t.z = __ldg(&coefs[j]);
        t.w = __int_as_float(hit);
        g_table[j] = t;
    }
}

// Main: out[b, j] = exp(-0.5*z^2)*coef,  z = (x[b,src[j]] - mean[j]) * inv_var[j]
// CTA: 256 threads, 1024 consecutive j (4/thread), 4 consecutive batch rows.
__global__ __launch_bounds__(256) void urbf_kernel(
    const float* __restrict__ x,
    float* __restrict__ out)
{
    int jblk = blockIdx.x & 3;                 // 4 j-blocks of 1024
    int rblk = blockIdx.x >> 2;                // 2048 row-blocks of 4
    int j = jblk * J_PER_CTA + threadIdx.x * 4;

    float4 t0 = g_table[j + 0];
    float4 t1 = g_table[j + 1];
    float4 t2 = g_table[j + 2];
    float4 t3 = g_table[j + 3];
    int s0 = __float_as_int(t0.w);
    int s1 = __float_as_int(t1.w);
    int s2 = __float_as_int(t2.w);
    int s3 = __float_as_int(t3.w);
    bool uni = (s0 == s1) && (s1 == s2) && (s2 == s3);

    const float* xbase = x + (size_t)rblk * R_PER_CTA * IN_FEATURES;
    float* obase = out + (size_t)rblk * R_PER_CTA * OUT_FEATURES + j;

    #pragma unroll
    for (int r = 0; r < R_PER_CTA; r++) {
        const float* xr = xbase + r * IN_FEATURES;
        float v0, v1, v2, v3;
        if (uni) {
            v0 = __ldg(xr + s0);
            v1 = v0; v2 = v0; v3 = v0;
        } else {
            v0 = __ldg(xr + s0);
            v1 = __ldg(xr + s1);
            v2 = __ldg(xr + s2);
            v3 = __ldg(xr + s3);
        }

        float z0 = (v0 - t0.x) * t0.y;
        float z1 = (v1 - t1.x) * t1.y;
        float z2 = (v2 - t2.x) * t2.y;
        float z3 = (v3 - t3.x) * t3.y;

        float4 o;
        o.x = __expf(-0.5f * z0 * z0) * t0.z;
        o.y = __expf(-0.5f * z1 * z1) * t1.z;
        o.z = __expf(-0.5f * z2 * z2) * t2.z;
        o.w = __expf(-0.5f * z3 * z3) * t3.z;

        __stcs(reinterpret_cast<float4*>(obase + (size_t)r * OUT_FEATURES), o);
    }
}

extern "C" void kernel_launch(void* const* d_in, const int* in_sizes, int n_in,
                              void* d_out, int out_size) {
    const float* x     = (const float*)d_in[0];  // [8192, 256]
    const float* em    = (const float*)d_in[1];  // [4096, 256]
    const float* means = (const float*)d_in[2];  // [4096]
    const float* vars_ = (const float*)d_in[3];  // [4096]
    const float* coefs = (const float*)d_in[4];  // [4096]
    float* out = (float*)d_out;                  // [8192, 4096]

    const int em_vec4 = OUT_FEATURES * IN_FEATURES / 4;      // 262,144
    build_table_kernel<<<em_vec4 / 256, 256>>>(
        (const float4*)em, means, vars_, coefs);

    const int nblocks = (OUT_FEATURES / J_PER_CTA) * (BATCH / R_PER_CTA);  // 8192
    urbf_kernel<<<nblocks, 256>>>(x, out);
}

// round 7
// speedup vs baseline: 1.2231x; 1.2231x over previous
#include <cuda_runtime.h>
#include <cuda_bf16.h>

#define IN_FEATURES  256
#define OUT_FEATURES 4096
#define BATCH        8192

#define J_PER_CTA    1024   // 256 threads x 4 j
#define R_PER_CTA    16     // batch rows per CTA

// Packed per-out-feature params: {mean, inv_var, coef, src_index_as_bits}
__device__ float4 g_table[OUT_FEATURES];

// Prologue: one thread per float4 of expansion_mapping (4096x256/4 = 256K threads).
__global__ void build_table_kernel(const float4* __restrict__ em4,
                                   const float* __restrict__ means,
                                   const float* __restrict__ vars_,
                                   const float* __restrict__ coefs) {
    int tid = blockIdx.x * blockDim.x + threadIdx.x;    // [0, OUT*IN/4)
    float4 e = em4[tid];
    int base_i = (tid & (IN_FEATURES / 4 - 1)) * 4;
    int j = tid >> 6;                                    // IN_FEATURES/4 = 64
    int hit = -1;
    if (e.x > 0.5f) hit = base_i + 0;
    if (e.y > 0.5f) hit = base_i + 1;
    if (e.z > 0.5f) hit = base_i + 2;
    if (e.w > 0.5f) hit = base_i + 3;
    if (hit >= 0) {
        float4 t;
        t.x = __ldg(&means[j]);
        t.y = 1.0f / __ldg(&vars_[j]);
        t.z = __ldg(&coefs[j]);
        t.w = __int_as_float(hit);
        g_table[j] = t;
    }
}

// Main: out[b, j] = exp(-0.5*z^2)*coef,  z = (x[b,src[j]] - mean[j]) * inv_var[j]
// CTA: 256 threads, 1024 consecutive j (4/thread), 16 consecutive batch rows.
__global__ __launch_bounds__(256) void urbf_kernel(
    const float* __restrict__ x,
    float* __restrict__ out)
{
    int jblk = blockIdx.x & 3;                 // 4 j-blocks of 1024
    int rblk = blockIdx.x >> 2;                // 512 row-blocks of 16
    int j = jblk * J_PER_CTA + threadIdx.x * 4;

    float4 t0 = g_table[j + 0];
    float4 t1 = g_table[j + 1];
    float4 t2 = g_table[j + 2];
    float4 t3 = g_table[j + 3];
    int s0 = __float_as_int(t0.w);
    int s1 = __float_as_int(t1.w);
    int s2 = __float_as_int(t2.w);
    int s3 = __float_as_int(t3.w);
    bool uni = (s0 == s1) && (s1 == s2) && (s2 == s3);

    const float* xbase = x + (size_t)rblk * R_PER_CTA * IN_FEATURES;
    float* obase = out + (size_t)rblk * R_PER_CTA * OUT_FEATURES + j;

    #pragma unroll
    for (int r = 0; r < R_PER_CTA; r++) {
        const float* xr = xbase + r * IN_FEATURES;
        float v0, v1, v2, v3;
        if (uni) {
            v0 = __ldg(xr + s0);
            v1 = v0; v2 = v0; v3 = v0;
        } else {
            v0 = __ldg(xr + s0);
            v1 = __ldg(xr + s1);
            v2 = __ldg(xr + s2);
            v3 = __ldg(xr + s3);
        }

        float z0 = (v0 - t0.x) * t0.y;
        float z1 = (v1 - t1.x) * t1.y;
        float z2 = (v2 - t2.x) * t2.y;
        float z3 = (v3 - t3.x) * t3.y;

        float4 o;
        o.x = __expf(-0.5f * z0 * z0) * t0.z;
        o.y = __expf(-0.5f * z1 * z1) * t1.z;
        o.z = __expf(-0.5f * z2 * z2) * t2.z;
        o.w = __expf(-0.5f * z3 * z3) * t3.z;

        __stcs(reinterpret_cast<float4*>(obase + (size_t)r * OUT_FEATURES), o);
    }
}

extern "C" void kernel_launch(void* const* d_in, const int* in_sizes, int n_in,
                              void* d_out, int out_size) {
    const float* x     = (const float*)d_in[0];  // [8192, 256]
    const float* em    = (const float*)d_in[1];  // [4096, 256]
    const float* means = (const float*)d_in[2];  // [4096]
    const float* vars_ = (const float*)d_in[3];  // [4096]
    const float* coefs = (const float*)d_in[4];  // [4096]
    float* out = (float*)d_out;                  // [8192, 4096]

    const int em_vec4 = OUT_FEATURES * IN_FEATURES / 4;      // 262,144
    build_table_kernel<<<em_vec4 / 256, 256>>>(
        (const float4*)em, means, vars_, coefs);

    const int nblocks = (OUT_FEATURES / J_PER_CTA) * (BATCH / R_PER_CTA);  // 2048
    urbf_kernel<<<nblocks, 256>>>(x, out);
}